// round 1
// baseline (speedup 1.0000x reference)
#include <cuda_runtime.h>
#include <math.h>
#include <stdint.h>

#define NV      6144
#define NFEAT   128
#define NHID    64
#define NHEAD   4
#define NCLASS  16
#define CAP     256
#define ALPHA   0.2f
#define NEGV    (-1e10f)

// ---------------- device scratch (no allocs allowed) ----------------
__device__ float g_Weff[NFEAT * NHEAD * NHID];        // [128][256]  summed-tile weights, head-major cols
__device__ float g_Hh[(size_t)NV * NHEAD * NHID];     // [N][256]    hidden features per head (pre-attn)
__device__ float g_s[NHEAD * NV];                     // attn_for_self  per head
__device__ float g_t[NHEAD * NV];                     // attn_for_neigh per head
__device__ int   g_nbr[(size_t)NV * CAP];             // per-row neighbor indices (ascending)
__device__ int   g_cnt[NV];                           // per-row nonzero count
__device__ float g_X2[(size_t)NV * NHEAD * NHID];     // [N][256]    elu(concat heads)
__device__ float g_H2[(size_t)NV * NCLASS];           // [N][16]
__device__ float g_s2[NV];
__device__ float g_t2[NV];

__device__ __forceinline__ float lrelu(float x) { return x > 0.f ? x : ALPHA * x; }
__device__ __forceinline__ float eluf(float x)  { return x > 0.f ? x : (expf(x) - 1.f); }

// ---------------- K1: Weff[k][h*64+c] = sum_t W0[h][(t*128+k)][c] ----------------
__global__ void k_weff(const float* __restrict__ W0) {
    int tid = blockIdx.x * blockDim.x + threadIdx.x;   // 32768 total
    if (tid >= NFEAT * NHEAD * NHID) return;
    int k = tid >> 8;          // 0..127
    int C = tid & 255;         // 0..255
    int h = C >> 6;
    int c = C & 63;
    const float* base = W0 + (size_t)h * 512 * 64;
    float v = 0.f;
#pragma unroll
    for (int t = 0; t < 4; t++) v += base[(t * 128 + k) * 64 + c];
    g_Weff[k * 256 + C] = v;
}

// ---------------- K2: g_Hh = feature[ N x 128 ] @ g_Weff[ 128 x 256 ] ----------------
// tile 64x64, Kchunk 64, block 256 (16x16 threads, 4x4 micro-tile)
__global__ void k_gemm_h(const float* __restrict__ feat) {
    __shared__ float As[64][64];   // [row][k]
    __shared__ float Bs[64][64];   // [k][c]
    int row0 = blockIdx.x * 64;
    int head = blockIdx.y;
    int tid = threadIdx.x;
    int tr = tid >> 4, tc = tid & 15;
    float acc[4][4] = {};
    for (int kc = 0; kc < 2; kc++) {
        for (int i = tid; i < 64 * 64; i += 256) {
            int r = i >> 6, q = i & 63;
            As[r][q] = feat[(size_t)(row0 + r) * NFEAT + kc * 64 + q];
            Bs[r][q] = g_Weff[(kc * 64 + r) * 256 + head * 64 + q];
        }
        __syncthreads();
#pragma unroll 8
        for (int k = 0; k < 64; k++) {
            float a0 = As[tr * 4 + 0][k], a1 = As[tr * 4 + 1][k];
            float a2 = As[tr * 4 + 2][k], a3 = As[tr * 4 + 3][k];
            float b0 = Bs[k][tc * 4 + 0], b1 = Bs[k][tc * 4 + 1];
            float b2 = Bs[k][tc * 4 + 2], b3 = Bs[k][tc * 4 + 3];
            acc[0][0] += a0 * b0; acc[0][1] += a0 * b1; acc[0][2] += a0 * b2; acc[0][3] += a0 * b3;
            acc[1][0] += a1 * b0; acc[1][1] += a1 * b1; acc[1][2] += a1 * b2; acc[1][3] += a1 * b3;
            acc[2][0] += a2 * b0; acc[2][1] += a2 * b1; acc[2][2] += a2 * b2; acc[2][3] += a2 * b3;
            acc[3][0] += a3 * b0; acc[3][1] += a3 * b1; acc[3][2] += a3 * b2; acc[3][3] += a3 * b3;
        }
        __syncthreads();
    }
#pragma unroll
    for (int m = 0; m < 4; m++)
#pragma unroll
        for (int n = 0; n < 4; n++)
            g_Hh[(size_t)(row0 + tr * 4 + m) * 256 + head * 64 + tc * 4 + n] = acc[m][n];
}

// ---------------- K3: s[h][i] = Hh_row(head h) . a1[h];  t likewise ----------------
// warp per row; lane handles 8 consecutive floats (32B coalesced)
__global__ void k_st(const float* __restrict__ a1, const float* __restrict__ a2) {
    int row = blockIdx.x * 8 + (threadIdx.x >> 5);
    int lane = threadIdx.x & 31;
    if (row >= NV) return;
    const float4* h4 = reinterpret_cast<const float4*>(g_Hh + (size_t)row * 256 + lane * 8);
    float4 v0 = h4[0], v1 = h4[1];
    int h = lane >> 3;
    int coff = (lane & 7) * 8;
    const float* pa1 = a1 + h * 64 + coff;
    const float* pa2 = a2 + h * 64 + coff;
    float sa = v0.x * pa1[0] + v0.y * pa1[1] + v0.z * pa1[2] + v0.w * pa1[3]
             + v1.x * pa1[4] + v1.y * pa1[5] + v1.z * pa1[6] + v1.w * pa1[7];
    float sb = v0.x * pa2[0] + v0.y * pa2[1] + v0.z * pa2[2] + v0.w * pa2[3]
             + v1.x * pa2[4] + v1.y * pa2[5] + v1.z * pa2[6] + v1.w * pa2[7];
#pragma unroll
    for (int o = 4; o > 0; o >>= 1) {
        sa += __shfl_down_sync(0xffffffffu, sa, o, 8);
        sb += __shfl_down_sync(0xffffffffu, sb, o, 8);
    }
    if ((lane & 7) == 0) {
        g_s[h * NV + row] = sa;
        g_t[h * NV + row] = sb;
    }
}

// ---------------- K4: ordered compaction of adj row nonzeros ----------------
__global__ void k_nbrs(const float* __restrict__ adj) {
    int row = blockIdx.x;
    const float4* a4 = reinterpret_cast<const float4*>(adj + (size_t)row * NV);
    __shared__ int warp_off[8];
    __shared__ int s_base;
    int tid = threadIdx.x, lane = tid & 31, wid = tid >> 5;
    if (tid == 0) s_base = 0;
    __syncthreads();
    int* out = g_nbr + (size_t)row * CAP;
    for (int start = 0; start < NV / 4; start += 256) {
        float4 v = a4[start + tid];
        int b0 = v.x != 0.f, b1 = v.y != 0.f, b2 = v.z != 0.f, b3 = v.w != 0.f;
        int cnt = b0 + b1 + b2 + b3;
        int incl = cnt;
#pragma unroll
        for (int o = 1; o < 32; o <<= 1) {
            int n = __shfl_up_sync(0xffffffffu, incl, o);
            if (lane >= o) incl += n;
        }
        if (lane == 31) warp_off[wid] = incl;
        __syncthreads();
        int wbase = 0, total = 0;
#pragma unroll
        for (int w = 0; w < 8; w++) {
            int wc = warp_off[w];
            if (w < wid) wbase += wc;
            total += wc;
        }
        int pos = s_base + wbase + incl - cnt;
        int j0 = (start + tid) * 4;
        if (b0) { if (pos < CAP) out[pos] = j0;     pos++; }
        if (b1) { if (pos < CAP) out[pos] = j0 + 1; pos++; }
        if (b2) { if (pos < CAP) out[pos] = j0 + 2; pos++; }
        if (b3) { if (pos < CAP) out[pos] = j0 + 3; pos++; }
        __syncthreads();
        if (tid == 0) s_base += total;
        __syncthreads();
    }
    if (tid == 0) g_cnt[row] = s_base;
}

// ---------------- K5: hidden sparse attention + elu -> g_X2 ----------------
// block = 256 = 4 groups of 64; group g handles head g; lane l = output column
__global__ void k_attn_hidden(const float* __restrict__ adj) {
    int row = blockIdx.x;
    int tid = threadIdx.x;
    int g = tid >> 6, l = tid & 63;
    __shared__ int   s_idx[CAP];
    __shared__ float s_w[NHEAD][CAP];
    __shared__ float red[256];
    __shared__ float s_stat[NHEAD];
    int cnt = g_cnt[row];
    bool sparse = (cnt > 0 && cnt <= CAP);
    if (sparse)
        for (int k = tid; k < cnt; k += 256) s_idx[k] = g_nbr[(size_t)row * CAP + k];
    __syncthreads();
    float s_i = g_s[g * NV + row];
    const float* tvec = g_t + g * NV;

    if (sparse) {
        float mx = -INFINITY;
        for (int k = l; k < cnt; k += 64) {
            float lv = lrelu(s_i + tvec[s_idx[k]]);
            s_w[g][k] = lv;
            mx = fmaxf(mx, lv);
        }
        red[tid] = mx; __syncthreads();
        if (l < 32) {
            float m = fmaxf(red[tid], red[tid + 32]);
#pragma unroll
            for (int o = 16; o > 0; o >>= 1) m = fmaxf(m, __shfl_xor_sync(0xffffffffu, m, o));
            if (l == 0) s_stat[g] = m;
        }
        __syncthreads();
        mx = s_stat[g];
        float sum = 0.f;
        for (int k = l; k < cnt; k += 64) {
            float e = expf(s_w[g][k] - mx);
            s_w[g][k] = e;
            sum += e;
        }
        __syncthreads();
        red[tid] = sum; __syncthreads();
        if (l < 32) {
            float s = red[tid] + red[tid + 32];
#pragma unroll
            for (int o = 16; o > 0; o >>= 1) s += __shfl_xor_sync(0xffffffffu, s, o);
            if (l == 0) s_stat[g] = s;
        }
        __syncthreads();
        float S = s_stat[g];
        float acc = 0.f;
        const float* hb = g_Hh + g * 64 + l;
#pragma unroll 4
        for (int k = 0; k < cnt; k++)
            acc += s_w[g][k] * hb[(size_t)s_idx[k] * 256];
        g_X2[(size_t)row * 256 + g * 64 + l] = eluf(acc / S);
    } else {
        // dense fallback (rows fully masked, or >CAP nonzeros; ~never taken)
        const float* arow = adj + (size_t)row * NV;
        float mx = -INFINITY;
        for (int j = l; j < NV; j += 64) {
            float lv = lrelu(s_i + tvec[j]);
            if (arow[j] == 0.f) lv += NEGV;
            mx = fmaxf(mx, lv);
        }
        red[tid] = mx; __syncthreads();
        if (l < 32) {
            float m = fmaxf(red[tid], red[tid + 32]);
#pragma unroll
            for (int o = 16; o > 0; o >>= 1) m = fmaxf(m, __shfl_xor_sync(0xffffffffu, m, o));
            if (l == 0) s_stat[g] = m;
        }
        __syncthreads();
        mx = s_stat[g];
        float sum = 0.f;
        for (int j = l; j < NV; j += 64) {
            float lv = lrelu(s_i + tvec[j]);
            if (arow[j] == 0.f) lv += NEGV;
            sum += expf(lv - mx);
        }
        __syncthreads();
        red[tid] = sum; __syncthreads();
        if (l < 32) {
            float s = red[tid] + red[tid + 32];
#pragma unroll
            for (int o = 16; o > 0; o >>= 1) s += __shfl_xor_sync(0xffffffffu, s, o);
            if (l == 0) s_stat[g] = s;
        }
        __syncthreads();
        float S = s_stat[g];
        float acc = 0.f;
        const float* hb = g_Hh + g * 64 + l;
        for (int j = 0; j < NV; j++) {
            float lv = lrelu(s_i + tvec[j]);
            if (arow[j] == 0.f) lv += NEGV;
            acc += expf(lv - mx) * hb[(size_t)j * 256];
        }
        g_X2[(size_t)row * 256 + g * 64 + l] = eluf(acc / S);
    }
}

// ---------------- K6: g_H2 = g_X2 @ Wout [256x16]; s2/t2 dots ----------------
__global__ void k_out_proj(const float* __restrict__ Wout,
                           const float* __restrict__ a1o, const float* __restrict__ a2o) {
    __shared__ float Ws[256 * 16];
    __shared__ float a1s[16], a2s[16];
    int tid = threadIdx.x;
    for (int i = tid; i < 256 * 16; i += 256) Ws[i] = Wout[i];
    if (tid < 16) { a1s[tid] = a1o[tid]; a2s[tid] = a2o[tid]; }
    __syncthreads();
    int row = blockIdx.x * 16 + (tid >> 4);
    int c = tid & 15;
    const float* x = g_X2 + (size_t)row * 256;
    float acc = 0.f;
#pragma unroll 8
    for (int k = 0; k < 256; k++) acc += x[k] * Ws[k * 16 + c];
    g_H2[(size_t)row * 16 + c] = acc;
    float sa = acc * a1s[c], sb = acc * a2s[c];
#pragma unroll
    for (int o = 8; o > 0; o >>= 1) {
        sa += __shfl_down_sync(0xffffffffu, sa, o, 16);
        sb += __shfl_down_sync(0xffffffffu, sb, o, 16);
    }
    if (c == 0) { g_s2[row] = sa; g_t2[row] = sb; }
}

// ---------------- K7: output sparse attention + elu + class softmax ----------------
__global__ void k_attn_out(const float* __restrict__ adj, float* __restrict__ out) {
    int row = blockIdx.x;
    int tid = threadIdx.x;  // 128
    __shared__ int   s_idx[CAP];
    __shared__ float s_w[CAP];
    __shared__ float red[128];
    __shared__ float s_stat;
    int cnt = g_cnt[row];
    bool sparse = (cnt > 0 && cnt <= CAP);
    float s_i = g_s2[row];

    float mx, S;
    if (sparse) {
        for (int k = tid; k < cnt; k += 128) s_idx[k] = g_nbr[(size_t)row * CAP + k];
        __syncthreads();
        float m = -INFINITY;
        for (int k = tid; k < cnt; k += 128) {
            float lv = lrelu(s_i + g_t2[s_idx[k]]);
            s_w[k] = lv;
            m = fmaxf(m, lv);
        }
        red[tid] = m; __syncthreads();
        if (tid < 64) red[tid] = fmaxf(red[tid], red[tid + 64]);
        __syncthreads();
        if (tid < 32) {
            float mm = fmaxf(red[tid], red[tid + 32]);
#pragma unroll
            for (int o = 16; o > 0; o >>= 1) mm = fmaxf(mm, __shfl_xor_sync(0xffffffffu, mm, o));
            if (tid == 0) s_stat = mm;
        }
        __syncthreads();
        mx = s_stat;
        float sum = 0.f;
        for (int k = tid; k < cnt; k += 128) {
            float e = expf(s_w[k] - mx);
            s_w[k] = e;
            sum += e;
        }
        __syncthreads();
        red[tid] = sum; __syncthreads();
        if (tid < 64) red[tid] += red[tid + 64];
        __syncthreads();
        if (tid < 32) {
            float ss = red[tid] + red[tid + 32];
#pragma unroll
            for (int o = 16; o > 0; o >>= 1) ss += __shfl_xor_sync(0xffffffffu, ss, o);
            if (tid == 0) s_stat = ss;
        }
        __syncthreads();
        S = s_stat;
        if (tid < 16) {
            float acc = 0.f;
#pragma unroll 4
            for (int k = 0; k < cnt; k++)
                acc += s_w[k] * g_H2[(size_t)s_idx[k] * 16 + tid];
            float v = eluf(acc / S);
            float m16 = v;
#pragma unroll
            for (int o = 8; o > 0; o >>= 1) m16 = fmaxf(m16, __shfl_xor_sync(0xffffu, m16, o, 16));
            float e = expf(v - m16);
            float se = e;
#pragma unroll
            for (int o = 8; o > 0; o >>= 1) se += __shfl_xor_sync(0xffffu, se, o, 16);
            out[(size_t)row * 16 + tid] = e / se;
        }
    } else {
        const float* arow = adj + (size_t)row * NV;
        float m = -INFINITY;
        for (int j = tid; j < NV; j += 128) {
            float lv = lrelu(s_i + g_t2[j]);
            if (arow[j] == 0.f) lv += NEGV;
            m = fmaxf(m, lv);
        }
        red[tid] = m; __syncthreads();
        if (tid < 64) red[tid] = fmaxf(red[tid], red[tid + 64]);
        __syncthreads();
        if (tid < 32) {
            float mm = fmaxf(red[tid], red[tid + 32]);
#pragma unroll
            for (int o = 16; o > 0; o >>= 1) mm = fmaxf(mm, __shfl_xor_sync(0xffffffffu, mm, o));
            if (tid == 0) s_stat = mm;
        }
        __syncthreads();
        mx = s_stat;
        float sum = 0.f;
        for (int j = tid; j < NV; j += 128) {
            float lv = lrelu(s_i + g_t2[j]);
            if (arow[j] == 0.f) lv += NEGV;
            sum += expf(lv - mx);
        }
        __syncthreads();
        red[tid] = sum; __syncthreads();
        if (tid < 64) red[tid] += red[tid + 64];
        __syncthreads();
        if (tid < 32) {
            float ss = red[tid] + red[tid + 32];
#pragma unroll
            for (int o = 16; o > 0; o >>= 1) ss += __shfl_xor_sync(0xffffffffu, ss, o);
            if (tid == 0) s_stat = ss;
        }
        __syncthreads();
        S = s_stat;
        if (tid < 16) {
            float acc = 0.f;
            for (int j = 0; j < NV; j++) {
                float lv = lrelu(s_i + g_t2[j]);
                if (arow[j] == 0.f) lv += NEGV;
                acc += expf(lv - mx) * g_H2[(size_t)j * 16 + tid];
            }
            float v = eluf(acc / S);
            float m16 = v;
#pragma unroll
            for (int o = 8; o > 0; o >>= 1) m16 = fmaxf(m16, __shfl_xor_sync(0xffffu, m16, o, 16));
            float e = expf(v - m16);
            float se = e;
#pragma unroll
            for (int o = 8; o > 0; o >>= 1) se += __shfl_xor_sync(0xffffu, se, o, 16);
            out[(size_t)row * 16 + tid] = e / se;
        }
    }
}

// ---------------- launch ----------------
extern "C" void kernel_launch(void* const* d_in, const int* in_sizes, int n_in,
                              void* d_out, int out_size) {
    const float* adj  = (const float*)d_in[0];
    const float* feat = (const float*)d_in[1];
    const float* W0   = (const float*)d_in[2];
    const float* a1_0 = (const float*)d_in[3];
    const float* a2_0 = (const float*)d_in[4];
    const float* Wout = (const float*)d_in[5];
    const float* a1o  = (const float*)d_in[6];
    const float* a2o  = (const float*)d_in[7];
    float* out = (float*)d_out;

    k_weff<<<(NFEAT * NHEAD * NHID + 255) / 256, 256>>>(W0);
    k_nbrs<<<NV, 256>>>(adj);                       // big streaming read of adj (one pass, reused by both layers)
    k_gemm_h<<<dim3(NV / 64, NHEAD), 256>>>(feat);
    k_st<<<NV / 8, 256>>>(a1_0, a2_0);
    k_attn_hidden<<<NV, 256>>>(adj);
    k_out_proj<<<NV / 16, 256>>>(Wout, a1o, a2o);
    k_attn_out<<<NV, 128>>>(adj, out);
}

// round 3
// speedup vs baseline: 1.2537x; 1.2537x over previous
#include <cuda_runtime.h>
#include <math.h>
#include <stdint.h>

#define NV      6144
#define NFEAT   128
#define NHID    64
#define NHEAD   4
#define NCLASS  16
#define CAP     256
#define ALPHA   0.2f
#define NEGV    (-1e10f)
#define AS_STRIDE 68   // 64 + 4 pad: 16B-aligned rows, 8 distinct banks for the 8 row-reads

// ---------------- device scratch ----------------
__device__ float g_Weff[NFEAT * NHEAD * NHID];        // [128][256] head-major cols
__device__ float g_Hh[(size_t)NV * NHEAD * NHID];     // [N][256]
__device__ float g_s[NHEAD * NV];
__device__ float g_t[NHEAD * NV];
__device__ int   g_nbr[(size_t)NV * CAP];
__device__ int   g_cnt[NV];
__device__ float g_X2[(size_t)NV * NHEAD * NHID];     // [N][256]
__device__ float g_H2[(size_t)NV * NCLASS];           // [N][16]
__device__ float g_s2[NV];
__device__ float g_t2[NV];

__device__ __forceinline__ float lrelu(float x) { return x > 0.f ? x : ALPHA * x; }
__device__ __forceinline__ float eluf(float x)  { return x > 0.f ? x : (expf(x) - 1.f); }

// ---------------- K1: Weff[k][h*64+c] = sum_t W0[h][(t*128+k)][c] ----------------
__global__ void k_weff(const float* __restrict__ W0) {
    int tid = blockIdx.x * blockDim.x + threadIdx.x;
    if (tid >= NFEAT * NHEAD * NHID) return;
    int k = tid >> 8, C = tid & 255;
    int h = C >> 6, c = C & 63;
    const float* base = W0 + (size_t)h * 512 * 64;
    float v = 0.f;
#pragma unroll
    for (int t = 0; t < 4; t++) v += base[(t * 128 + k) * 64 + c];
    g_Weff[k * 256 + C] = v;
}

// ---------------- K2: nbr compaction, MLP=6 batched loads, single scan ----------------
__global__ void k_nbrs(const float* __restrict__ adj) {
    int row = blockIdx.x;
    int tid = threadIdx.x, lane = tid & 31, wid = tid >> 5;
    const uint4* a4 = reinterpret_cast<const uint4*>(adj) + (size_t)row * (NV / 4);
    uint4 v[6];
#pragma unroll
    for (int it = 0; it < 6; it++) v[it] = __ldg(&a4[it * 256 + tid]);
    unsigned mask = 0;
#pragma unroll
    for (int it = 0; it < 6; it++) {
        if (v[it].x) mask |= 1u << (it * 4 + 0);
        if (v[it].y) mask |= 1u << (it * 4 + 1);
        if (v[it].z) mask |= 1u << (it * 4 + 2);
        if (v[it].w) mask |= 1u << (it * 4 + 3);
    }
    int cnt = __popc(mask);
    int incl = cnt;
#pragma unroll
    for (int o = 1; o < 32; o <<= 1) {
        int n = __shfl_up_sync(0xffffffffu, incl, o);
        if (lane >= o) incl += n;
    }
    __shared__ int wsum[8];
    if (lane == 31) wsum[wid] = incl;
    __syncthreads();
    int base = 0;
#pragma unroll
    for (int w = 0; w < 8; w++) if (w < wid) base += wsum[w];
    int pos = base + incl - cnt;
    int* out = g_nbr + (size_t)row * CAP;
    while (mask) {
        int b = __ffs(mask) - 1;
        mask &= mask - 1;
        if (pos < CAP) out[pos] = (b >> 2) * 1024 + tid * 4 + (b & 3);
        pos++;
    }
    if (tid == 255) g_cnt[row] = base + incl;
}

// ---------------- K3: g_Hh = feat @ Weff (per head), fused s/t epilogue ----------------
__global__ void k_gemm_h(const float* __restrict__ feat,
                         const float* __restrict__ a1g, const float* __restrict__ a2g) {
    __shared__ float As[64 * AS_STRIDE];   // [r][k] padded
    __shared__ float Bs[64 * 64];          // [k][c]
    int row0 = blockIdx.x * 64;
    int head = blockIdx.y;
    int tid = threadIdx.x;
    int tr = tid >> 4, tc = tid & 15;
    float acc[4][4] = {};
    const float4* feat4 = reinterpret_cast<const float4*>(feat);
    const float4* weff4 = reinterpret_cast<const float4*>(g_Weff);
    for (int kc = 0; kc < 2; kc++) {
#pragma unroll
        for (int it = 0; it < 4; it++) {
            int idx = it * 256 + tid;      // 1024 float4 of A chunk
            int r = idx >> 4;              // 16 float4 per 64-float row
            int c4 = idx & 15;
            float4 v = feat4[(size_t)(row0 + r) * 32 + kc * 16 + c4];
            *reinterpret_cast<float4*>(&As[r * AS_STRIDE + c4 * 4]) = v;
        }
#pragma unroll
        for (int it = 0; it < 4; it++) {
            int idx = it * 256 + tid;
            int k = idx >> 4;
            int c4 = idx & 15;
            float4 v = weff4[(size_t)(kc * 64 + k) * 64 + head * 16 + c4];
            *reinterpret_cast<float4*>(&Bs[k * 64 + c4 * 4]) = v;
        }
        __syncthreads();
#pragma unroll 4
        for (int k = 0; k < 64; k++) {
            float4 bv = *reinterpret_cast<const float4*>(&Bs[k * 64 + tc * 4]);
            float a0 = As[(tr * 4 + 0) * AS_STRIDE + k];
            float a1 = As[(tr * 4 + 1) * AS_STRIDE + k];
            float a2 = As[(tr * 4 + 2) * AS_STRIDE + k];
            float a3 = As[(tr * 4 + 3) * AS_STRIDE + k];
            acc[0][0] += a0 * bv.x; acc[0][1] += a0 * bv.y; acc[0][2] += a0 * bv.z; acc[0][3] += a0 * bv.w;
            acc[1][0] += a1 * bv.x; acc[1][1] += a1 * bv.y; acc[1][2] += a1 * bv.z; acc[1][3] += a1 * bv.w;
            acc[2][0] += a2 * bv.x; acc[2][1] += a2 * bv.y; acc[2][2] += a2 * bv.z; acc[2][3] += a2 * bv.w;
            acc[3][0] += a3 * bv.x; acc[3][1] += a3 * bv.y; acc[3][2] += a3 * bv.z; acc[3][3] += a3 * bv.w;
        }
        __syncthreads();
    }
    // epilogue: store H rows + fused s/t dot products
    float a1r[4], a2r[4];
#pragma unroll
    for (int n = 0; n < 4; n++) {
        a1r[n] = __ldg(&a1g[head * 64 + tc * 4 + n]);
        a2r[n] = __ldg(&a2g[head * 64 + tc * 4 + n]);
    }
    float sp[4], tp[4];
#pragma unroll
    for (int m = 0; m < 4; m++) {
        float4 o;
        o.x = acc[m][0]; o.y = acc[m][1]; o.z = acc[m][2]; o.w = acc[m][3];
        *reinterpret_cast<float4*>(&g_Hh[(size_t)(row0 + tr * 4 + m) * 256 + head * 64 + tc * 4]) = o;
        sp[m] = acc[m][0] * a1r[0] + acc[m][1] * a1r[1] + acc[m][2] * a1r[2] + acc[m][3] * a1r[3];
        tp[m] = acc[m][0] * a2r[0] + acc[m][1] * a2r[1] + acc[m][2] * a2r[2] + acc[m][3] * a2r[3];
    }
#pragma unroll
    for (int o = 8; o > 0; o >>= 1) {
#pragma unroll
        for (int m = 0; m < 4; m++) {
            sp[m] += __shfl_down_sync(0xffffffffu, sp[m], o, 16);
            tp[m] += __shfl_down_sync(0xffffffffu, tp[m], o, 16);
        }
    }
    if (tc == 0) {
#pragma unroll
        for (int m = 0; m < 4; m++) {
            g_s[head * NV + row0 + tr * 4 + m] = sp[m];
            g_t[head * NV + row0 + tr * 4 + m] = tp[m];
        }
    }
}

// ---------------- K4: hidden sparse attention + elu -> g_X2 ----------------
__global__ void k_attn_hidden(const float* __restrict__ adj) {
    int row = blockIdx.x;
    int tid = threadIdx.x;
    int g = tid >> 6, l = tid & 63;
    __shared__ int   s_idx[CAP];
    __shared__ float s_w[NHEAD][CAP];
    __shared__ float red[256];
    __shared__ float s_stat[NHEAD];
    int cnt = g_cnt[row];
    bool sparse = (cnt > 0 && cnt <= CAP);
    if (sparse)
        for (int k = tid; k < cnt; k += 256) s_idx[k] = g_nbr[(size_t)row * CAP + k];
    __syncthreads();
    float s_i = g_s[g * NV + row];
    const float* tvec = g_t + g * NV;

    if (sparse) {
        float mx = -INFINITY;
        for (int k = l; k < cnt; k += 64) {
            float lv = lrelu(s_i + __ldg(&tvec[s_idx[k]]));
            s_w[g][k] = lv;
            mx = fmaxf(mx, lv);
        }
        red[tid] = mx; __syncthreads();
        if (l < 32) {
            float m = fmaxf(red[tid], red[tid + 32]);
#pragma unroll
            for (int o = 16; o > 0; o >>= 1) m = fmaxf(m, __shfl_xor_sync(0xffffffffu, m, o));
            if (l == 0) s_stat[g] = m;
        }
        __syncthreads();
        mx = s_stat[g];
        float sum = 0.f;
        for (int k = l; k < cnt; k += 64) {
            float e = expf(s_w[g][k] - mx);
            s_w[g][k] = e;
            sum += e;
        }
        __syncthreads();
        red[tid] = sum; __syncthreads();
        if (l < 32) {
            float s = red[tid] + red[tid + 32];
#pragma unroll
            for (int o = 16; o > 0; o >>= 1) s += __shfl_xor_sync(0xffffffffu, s, o);
            if (l == 0) s_stat[g] = s;
        }
        __syncthreads();
        float S = s_stat[g];
        float acc = 0.f;
        const float* hb = g_Hh + g * 64 + l;
#pragma unroll 4
        for (int k = 0; k < cnt; k++)
            acc += s_w[g][k] * __ldg(&hb[(size_t)s_idx[k] * 256]);
        g_X2[(size_t)row * 256 + g * 64 + l] = eluf(acc / S);
    } else {
        const float* arow = adj + (size_t)row * NV;
        float mx = -INFINITY;
        for (int j = l; j < NV; j += 64) {
            float lv = lrelu(s_i + tvec[j]);
            if (arow[j] == 0.f) lv += NEGV;
            mx = fmaxf(mx, lv);
        }
        red[tid] = mx; __syncthreads();
        if (l < 32) {
            float m = fmaxf(red[tid], red[tid + 32]);
#pragma unroll
            for (int o = 16; o > 0; o >>= 1) m = fmaxf(m, __shfl_xor_sync(0xffffffffu, m, o));
            if (l == 0) s_stat[g] = m;
        }
        __syncthreads();
        mx = s_stat[g];
        float sum = 0.f;
        for (int j = l; j < NV; j += 64) {
            float lv = lrelu(s_i + tvec[j]);
            if (arow[j] == 0.f) lv += NEGV;
            sum += expf(lv - mx);
        }
        __syncthreads();
        red[tid] = sum; __syncthreads();
        if (l < 32) {
            float s = red[tid] + red[tid + 32];
#pragma unroll
            for (int o = 16; o > 0; o >>= 1) s += __shfl_xor_sync(0xffffffffu, s, o);
            if (l == 0) s_stat[g] = s;
        }
        __syncthreads();
        float S = s_stat[g];
        float acc = 0.f;
        const float* hb = g_Hh + g * 64 + l;
        for (int j = 0; j < NV; j++) {
            float lv = lrelu(s_i + tvec[j]);
            if (arow[j] == 0.f) lv += NEGV;
            acc += expf(lv - mx) * hb[(size_t)j * 256];
        }
        g_X2[(size_t)row * 256 + g * 64 + l] = eluf(acc / S);
    }
}

// ---------------- K5: g_H2 = g_X2 @ Wout; s2/t2 ----------------
__global__ void k_out_proj(const float* __restrict__ Wout,
                           const float* __restrict__ a1o, const float* __restrict__ a2o) {
    __shared__ float Ws[256 * 16];
    __shared__ float a1s[16], a2s[16];
    int tid = threadIdx.x;
    for (int i = tid; i < 256 * 16; i += 256) Ws[i] = Wout[i];
    if (tid < 16) { a1s[tid] = a1o[tid]; a2s[tid] = a2o[tid]; }
    __syncthreads();
    int row = blockIdx.x * 16 + (tid >> 4);
    int c = tid & 15;
    const float* x = g_X2 + (size_t)row * 256;
    float acc = 0.f;
#pragma unroll 8
    for (int k = 0; k < 256; k++) acc += x[k] * Ws[k * 16 + c];
    g_H2[(size_t)row * 16 + c] = acc;
    float sa = acc * a1s[c], sb = acc * a2s[c];
#pragma unroll
    for (int o = 8; o > 0; o >>= 1) {
        sa += __shfl_down_sync(0xffffffffu, sa, o, 16);
        sb += __shfl_down_sync(0xffffffffu, sb, o, 16);
    }
    if (c == 0) { g_s2[row] = sa; g_t2[row] = sb; }
}

// ---------------- K6: output sparse attention + elu + class softmax ----------------
__global__ void k_attn_out(const float* __restrict__ adj, float* __restrict__ out) {
    int row = blockIdx.x;
    int tid = threadIdx.x;  // 128
    __shared__ int   s_idx[CAP];
    __shared__ float s_w[CAP];
    __shared__ float red[128];
    __shared__ float s_stat;
    int cnt = g_cnt[row];
    bool sparse = (cnt > 0 && cnt <= CAP);
    float s_i = g_s2[row];

    float mx, S;
    if (sparse) {
        for (int k = tid; k < cnt; k += 128) s_idx[k] = g_nbr[(size_t)row * CAP + k];
        __syncthreads();
        float m = -INFINITY;
        for (int k = tid; k < cnt; k += 128) {
            float lv = lrelu(s_i + __ldg(&g_t2[s_idx[k]]));
            s_w[k] = lv;
            m = fmaxf(m, lv);
        }
        red[tid] = m; __syncthreads();
        if (tid < 64) red[tid] = fmaxf(red[tid], red[tid + 64]);
        __syncthreads();
        if (tid < 32) {
            float mm = fmaxf(red[tid], red[tid + 32]);
#pragma unroll
            for (int o = 16; o > 0; o >>= 1) mm = fmaxf(mm, __shfl_xor_sync(0xffffffffu, mm, o));
            if (tid == 0) s_stat = mm;
        }
        __syncthreads();
        mx = s_stat;
        float sum = 0.f;
        for (int k = tid; k < cnt; k += 128) {
            float e = expf(s_w[k] - mx);
            s_w[k] = e;
            sum += e;
        }
        __syncthreads();
        red[tid] = sum; __syncthreads();
        if (tid < 64) red[tid] += red[tid + 64];
        __syncthreads();
        if (tid < 32) {
            float ss = red[tid] + red[tid + 32];
#pragma unroll
            for (int o = 16; o > 0; o >>= 1) ss += __shfl_xor_sync(0xffffffffu, ss, o);
            if (tid == 0) s_stat = ss;
        }
        __syncthreads();
        S = s_stat;
        if (tid < 16) {
            float acc = 0.f;
#pragma unroll 4
            for (int k = 0; k < cnt; k++)
                acc += s_w[k] * __ldg(&g_H2[(size_t)s_idx[k] * 16 + tid]);
            float v = eluf(acc / S);
            float m16 = v;
#pragma unroll
            for (int o = 8; o > 0; o >>= 1) m16 = fmaxf(m16, __shfl_xor_sync(0xffffu, m16, o, 16));
            float e = expf(v - m16);
            float se = e;
#pragma unroll
            for (int o = 8; o > 0; o >>= 1) se += __shfl_xor_sync(0xffffu, se, o, 16);
            out[(size_t)row * 16 + tid] = e / se;
        }
    } else {
        const float* arow = adj + (size_t)row * NV;
        float m = -INFINITY;
        for (int j = tid; j < NV; j += 128) {
            float lv = lrelu(s_i + g_t2[j]);
            if (arow[j] == 0.f) lv += NEGV;
            m = fmaxf(m, lv);
        }
        red[tid] = m; __syncthreads();
        if (tid < 64) red[tid] = fmaxf(red[tid], red[tid + 64]);
        __syncthreads();
        if (tid < 32) {
            float mm = fmaxf(red[tid], red[tid + 32]);
#pragma unroll
            for (int o = 16; o > 0; o >>= 1) mm = fmaxf(mm, __shfl_xor_sync(0xffffffffu, mm, o));
            if (tid == 0) s_stat = mm;
        }
        __syncthreads();
        mx = s_stat;
        float sum = 0.f;
        for (int j = tid; j < NV; j += 128) {
            float lv = lrelu(s_i + g_t2[j]);
            if (arow[j] == 0.f) lv += NEGV;
            sum += expf(lv - mx);
        }
        __syncthreads();
        red[tid] = sum; __syncthreads();
        if (tid < 64) red[tid] += red[tid + 64];
        __syncthreads();
        if (tid < 32) {
            float ss = red[tid] + red[tid + 32];
#pragma unroll
            for (int o = 16; o > 0; o >>= 1) ss += __shfl_xor_sync(0xffffffffu, ss, o);
            if (tid == 0) s_stat = ss;
        }
        __syncthreads();
        S = s_stat;
        if (tid < 16) {
            float acc = 0.f;
            for (int j = 0; j < NV; j++) {
                float lv = lrelu(s_i + g_t2[j]);
                if (arow[j] == 0.f) lv += NEGV;
                acc += expf(lv - mx) * g_H2[(size_t)j * 16 + tid];
            }
            float v = eluf(acc / S);
            float m16 = v;
#pragma unroll
            for (int o = 8; o > 0; o >>= 1) m16 = fmaxf(m16, __shfl_xor_sync(0xffffu, m16, o, 16));
            float e = expf(v - m16);
            float se = e;
#pragma unroll
            for (int o = 8; o > 0; o >>= 1) se += __shfl_xor_sync(0xffffu, se, o, 16);
            out[(size_t)row * 16 + tid] = e / se;
        }
    }
}

// ---------------- launch ----------------
extern "C" void kernel_launch(void* const* d_in, const int* in_sizes, int n_in,
                              void* d_out, int out_size) {
    const float* adj  = (const float*)d_in[0];
    const float* feat = (const float*)d_in[1];
    const float* W0   = (const float*)d_in[2];
    const float* a1_0 = (const float*)d_in[3];
    const float* a2_0 = (const float*)d_in[4];
    const float* Wout = (const float*)d_in[5];
    const float* a1o  = (const float*)d_in[6];
    const float* a2o  = (const float*)d_in[7];
    float* out = (float*)d_out;

    k_nbrs<<<NV, 256>>>(adj);                 // 151MB streaming scan first
    k_weff<<<(NFEAT * NHEAD * NHID + 255) / 256, 256>>>(W0);
    k_gemm_h<<<dim3(NV / 64, NHEAD), 256>>>(feat, a1_0, a2_0);
    k_attn_hidden<<<NV, 256>>>(adj);
    k_out_proj<<<NV / 16, 256>>>(Wout, a1o, a2o);
    k_attn_out<<<NV, 128>>>(adj, out);
}

// round 4
// speedup vs baseline: 1.3927x; 1.1109x over previous
#include <cuda_runtime.h>
#include <math.h>
#include <stdint.h>

#define NV      6144
#define NFEAT   128
#define NHID    64
#define NHEAD   4
#define NCLASS  16
#define CAP     256
#define ALPHA   0.2f
#define NEGV    (-1e10f)
#define AS_STRIDE 68
#define GEMM_BLOCKS 384   // (6144/64) row-tiles * 4 heads

// ---------------- device scratch ----------------
__device__ float g_Weff[NFEAT * NHEAD * NHID];
__device__ float g_Hh[(size_t)NV * NHEAD * NHID];
__device__ float g_s[NHEAD * NV];
__device__ float g_t[NHEAD * NV];
__device__ int   g_nbr[(size_t)NV * CAP];
__device__ int   g_cnt[NV];
__device__ float g_X2[(size_t)NV * NHEAD * NHID];
__device__ float g_H2[(size_t)NV * NCLASS];
__device__ float g_s2[NV];
__device__ float g_t2[NV];

__device__ __forceinline__ float lrelu(float x) { return x > 0.f ? x : ALPHA * x; }
__device__ __forceinline__ float eluf(float x)  { return x > 0.f ? x : (expf(x) - 1.f); }

// ---------------- K1: Weff ----------------
__global__ void k_weff(const float* __restrict__ W0) {
    int tid = blockIdx.x * blockDim.x + threadIdx.x;
    if (tid >= NFEAT * NHEAD * NHID) return;
    int k = tid >> 8, C = tid & 255;
    int h = C >> 6, c = C & 63;
    const float* base = W0 + (size_t)h * 512 * 64;
    float v = 0.f;
#pragma unroll
    for (int t = 0; t < 4; t++) v += base[(t * 128 + k) * 64 + c];
    g_Weff[k * 256 + C] = v;
}

// ---------------- K2 fat kernel: blocks [0,384) GEMM+s/t, blocks [384,6528) nbr compaction ----------------
__global__ void __launch_bounds__(256) k_main(const float* __restrict__ adj,
                                              const float* __restrict__ feat,
                                              const float* __restrict__ a1g,
                                              const float* __restrict__ a2g) {
    __shared__ float As[64 * AS_STRIDE];
    __shared__ float Bs[64 * 64];
    __shared__ int wsum[8];
    int tid = threadIdx.x;

    if (blockIdx.x < GEMM_BLOCKS) {
        // ---------- GEMM part: g_Hh tile + fused s/t dot ----------
        int head = blockIdx.x & 3;
        int row0 = (blockIdx.x >> 2) * 64;
        int tr = tid >> 4, tc = tid & 15;
        float acc[4][4] = {};
        const float4* feat4 = reinterpret_cast<const float4*>(feat);
        const float4* weff4 = reinterpret_cast<const float4*>(g_Weff);
        for (int kc = 0; kc < 2; kc++) {
#pragma unroll
            for (int it = 0; it < 4; it++) {
                int idx = it * 256 + tid;
                int r = idx >> 4, c4 = idx & 15;
                float4 v = feat4[(size_t)(row0 + r) * 32 + kc * 16 + c4];
                *reinterpret_cast<float4*>(&As[r * AS_STRIDE + c4 * 4]) = v;
            }
#pragma unroll
            for (int it = 0; it < 4; it++) {
                int idx = it * 256 + tid;
                int k = idx >> 4, c4 = idx & 15;
                float4 v = weff4[(size_t)(kc * 64 + k) * 64 + head * 16 + c4];
                *reinterpret_cast<float4*>(&Bs[k * 64 + c4 * 4]) = v;
            }
            __syncthreads();
#pragma unroll 4
            for (int k = 0; k < 64; k++) {
                float4 bv = *reinterpret_cast<const float4*>(&Bs[k * 64 + tc * 4]);
                float a0 = As[(tr * 4 + 0) * AS_STRIDE + k];
                float a1 = As[(tr * 4 + 1) * AS_STRIDE + k];
                float a2 = As[(tr * 4 + 2) * AS_STRIDE + k];
                float a3 = As[(tr * 4 + 3) * AS_STRIDE + k];
                acc[0][0] += a0 * bv.x; acc[0][1] += a0 * bv.y; acc[0][2] += a0 * bv.z; acc[0][3] += a0 * bv.w;
                acc[1][0] += a1 * bv.x; acc[1][1] += a1 * bv.y; acc[1][2] += a1 * bv.z; acc[1][3] += a1 * bv.w;
                acc[2][0] += a2 * bv.x; acc[2][1] += a2 * bv.y; acc[2][2] += a2 * bv.z; acc[2][3] += a2 * bv.w;
                acc[3][0] += a3 * bv.x; acc[3][1] += a3 * bv.y; acc[3][2] += a3 * bv.z; acc[3][3] += a3 * bv.w;
            }
            __syncthreads();
        }
        float a1r[4], a2r[4];
#pragma unroll
        for (int n = 0; n < 4; n++) {
            a1r[n] = __ldg(&a1g[head * 64 + tc * 4 + n]);
            a2r[n] = __ldg(&a2g[head * 64 + tc * 4 + n]);
        }
        float sp[4], tp[4];
#pragma unroll
        for (int m = 0; m < 4; m++) {
            float4 o;
            o.x = acc[m][0]; o.y = acc[m][1]; o.z = acc[m][2]; o.w = acc[m][3];
            *reinterpret_cast<float4*>(&g_Hh[(size_t)(row0 + tr * 4 + m) * 256 + head * 64 + tc * 4]) = o;
            sp[m] = acc[m][0] * a1r[0] + acc[m][1] * a1r[1] + acc[m][2] * a1r[2] + acc[m][3] * a1r[3];
            tp[m] = acc[m][0] * a2r[0] + acc[m][1] * a2r[1] + acc[m][2] * a2r[2] + acc[m][3] * a2r[3];
        }
#pragma unroll
        for (int o = 8; o > 0; o >>= 1) {
#pragma unroll
            for (int m = 0; m < 4; m++) {
                sp[m] += __shfl_down_sync(0xffffffffu, sp[m], o, 16);
                tp[m] += __shfl_down_sync(0xffffffffu, tp[m], o, 16);
            }
        }
        if (tc == 0) {
#pragma unroll
            for (int m = 0; m < 4; m++) {
                g_s[head * NV + row0 + tr * 4 + m] = sp[m];
                g_t[head * NV + row0 + tr * 4 + m] = tp[m];
            }
        }
    } else {
        // ---------- nbr compaction part ----------
        int row = blockIdx.x - GEMM_BLOCKS;
        int lane = tid & 31, wid = tid >> 5;
        const uint4* a4 = reinterpret_cast<const uint4*>(adj) + (size_t)row * (NV / 4);
        uint4 v[6];
#pragma unroll
        for (int it = 0; it < 6; it++) v[it] = __ldg(&a4[it * 256 + tid]);
        unsigned mask = 0;
#pragma unroll
        for (int it = 0; it < 6; it++) {
            if (v[it].x) mask |= 1u << (it * 4 + 0);
            if (v[it].y) mask |= 1u << (it * 4 + 1);
            if (v[it].z) mask |= 1u << (it * 4 + 2);
            if (v[it].w) mask |= 1u << (it * 4 + 3);
        }
        int cnt = __popc(mask);
        int incl = cnt;
#pragma unroll
        for (int o = 1; o < 32; o <<= 1) {
            int n = __shfl_up_sync(0xffffffffu, incl, o);
            if (lane >= o) incl += n;
        }
        if (lane == 31) wsum[wid] = incl;
        __syncthreads();
        int base = 0;
#pragma unroll
        for (int w = 0; w < 8; w++) if (w < wid) base += wsum[w];
        int pos = base + incl - cnt;
        int* out = g_nbr + (size_t)row * CAP;
        while (mask) {
            int b = __ffs(mask) - 1;
            mask &= mask - 1;
            if (pos < CAP) out[pos] = (b >> 2) * 1024 + tid * 4 + (b & 3);
            pos++;
        }
        if (tid == 255) g_cnt[row] = base + incl;
    }
}

// ---------------- K3: hidden sparse attention + elu -> g_X2 (neighbor-parallel) ----------------
__global__ void __launch_bounds__(256) k_attn_hidden(const float* __restrict__ adj) {
    int row = blockIdx.x;
    int tid = threadIdx.x;
    int g = tid >> 6, l = tid & 63;
    __shared__ int    s_idx[CAP];
    __shared__ float  s_w[NHEAD][CAP];
    __shared__ float  red[256];
    __shared__ float  s_stat[NHEAD];
    __shared__ float4 part[4][64];
    int cnt = g_cnt[row];
    bool sparse = (cnt > 0 && cnt <= CAP);
    if (sparse)
        for (int k = tid; k < cnt; k += 256) s_idx[k] = g_nbr[(size_t)row * CAP + k];
    __syncthreads();
    float s_i = g_s[g * NV + row];
    const float* tvec = g_t + g * NV;

    if (sparse) {
        // softmax weights per head (group g handles head g, stride 64)
        float mx = -INFINITY;
        for (int k = l; k < cnt; k += 64) {
            float lv = lrelu(s_i + __ldg(&tvec[s_idx[k]]));
            s_w[g][k] = lv;
            mx = fmaxf(mx, lv);
        }
        red[tid] = mx; __syncthreads();
        if (l < 32) {
            float m = fmaxf(red[tid], red[tid + 32]);
#pragma unroll
            for (int o = 16; o > 0; o >>= 1) m = fmaxf(m, __shfl_xor_sync(0xffffffffu, m, o));
            if (l == 0) s_stat[g] = m;
        }
        __syncthreads();
        mx = s_stat[g];
        float sum = 0.f;
        for (int k = l; k < cnt; k += 64) {
            float e = expf(s_w[g][k] - mx);
            s_w[g][k] = e;
            sum += e;
        }
        __syncthreads();
        red[tid] = sum; __syncthreads();
        if (l < 32) {
            float s = red[tid] + red[tid + 32];
#pragma unroll
            for (int o = 16; o > 0; o >>= 1) s += __shfl_xor_sync(0xffffffffu, s, o);
            if (l == 0) s_stat[g] = s;
        }
        __syncthreads();
        // weighted sum: q = neighbor phase (4-way), c4 = float4 column
        int q = g;            // 0..3
        int c4 = l;           // 0..63 -> cols 4*c4..4*c4+3, head = c4>>4
        int hh = c4 >> 4;
        float4 acc = make_float4(0.f, 0.f, 0.f, 0.f);
        const float4* hh4 = reinterpret_cast<const float4*>(g_Hh);
        for (int k = q; k < cnt; k += 4) {
            float w = s_w[hh][k];
            float4 v = __ldg(&hh4[(size_t)s_idx[k] * 64 + c4]);
            acc.x += w * v.x; acc.y += w * v.y; acc.z += w * v.z; acc.w += w * v.w;
        }
        part[q][c4] = acc;
        __syncthreads();
        if (q == 0) {
            float4 p0 = part[0][c4], p1 = part[1][c4], p2 = part[2][c4], p3 = part[3][c4];
            float S = s_stat[hh];
            float4 o;
            o.x = eluf((p0.x + p1.x + p2.x + p3.x) / S);
            o.y = eluf((p0.y + p1.y + p2.y + p3.y) / S);
            o.z = eluf((p0.z + p1.z + p2.z + p3.z) / S);
            o.w = eluf((p0.w + p1.w + p2.w + p3.w) / S);
            *reinterpret_cast<float4*>(&g_X2[(size_t)row * 256 + c4 * 4]) = o;
        }
    } else {
        // dense fallback (rare)
        const float* arow = adj + (size_t)row * NV;
        float mx = -INFINITY;
        for (int j = l; j < NV; j += 64) {
            float lv = lrelu(s_i + tvec[j]);
            if (arow[j] == 0.f) lv += NEGV;
            mx = fmaxf(mx, lv);
        }
        red[tid] = mx; __syncthreads();
        if (l < 32) {
            float m = fmaxf(red[tid], red[tid + 32]);
#pragma unroll
            for (int o = 16; o > 0; o >>= 1) m = fmaxf(m, __shfl_xor_sync(0xffffffffu, m, o));
            if (l == 0) s_stat[g] = m;
        }
        __syncthreads();
        mx = s_stat[g];
        float sum = 0.f;
        for (int j = l; j < NV; j += 64) {
            float lv = lrelu(s_i + tvec[j]);
            if (arow[j] == 0.f) lv += NEGV;
            sum += expf(lv - mx);
        }
        __syncthreads();
        red[tid] = sum; __syncthreads();
        if (l < 32) {
            float s = red[tid] + red[tid + 32];
#pragma unroll
            for (int o = 16; o > 0; o >>= 1) s += __shfl_xor_sync(0xffffffffu, s, o);
            if (l == 0) s_stat[g] = s;
        }
        __syncthreads();
        float S = s_stat[g];
        float acc = 0.f;
        const float* hb = g_Hh + g * 64 + l;
        for (int j = 0; j < NV; j++) {
            float lv = lrelu(s_i + tvec[j]);
            if (arow[j] == 0.f) lv += NEGV;
            acc += expf(lv - mx) * hb[(size_t)j * 256];
        }
        g_X2[(size_t)row * 256 + g * 64 + l] = eluf(acc / S);
    }
}

// ---------------- K4: g_H2 = g_X2 @ Wout; s2/t2 ----------------
__global__ void k_out_proj(const float* __restrict__ Wout,
                           const float* __restrict__ a1o, const float* __restrict__ a2o) {
    __shared__ float Ws[256 * 16];
    __shared__ float a1s[16], a2s[16];
    int tid = threadIdx.x;
    for (int i = tid; i < 256 * 16; i += 256) Ws[i] = Wout[i];
    if (tid < 16) { a1s[tid] = a1o[tid]; a2s[tid] = a2o[tid]; }
    __syncthreads();
    int row = blockIdx.x * 16 + (tid >> 4);
    int c = tid & 15;
    const float* x = g_X2 + (size_t)row * 256;
    float acc = 0.f;
#pragma unroll 8
    for (int k = 0; k < 256; k++) acc += x[k] * Ws[k * 16 + c];
    g_H2[(size_t)row * 16 + c] = acc;
    float sa = acc * a1s[c], sb = acc * a2s[c];
#pragma unroll
    for (int o = 8; o > 0; o >>= 1) {
        sa += __shfl_down_sync(0xffffffffu, sa, o, 16);
        sb += __shfl_down_sync(0xffffffffu, sb, o, 16);
    }
    if (c == 0) { g_s2[row] = sa; g_t2[row] = sb; }
}

// ---------------- K5: output sparse attention + elu + class softmax (neighbor-parallel) ----------------
__global__ void __launch_bounds__(128) k_attn_out(const float* __restrict__ adj, float* __restrict__ out) {
    int row = blockIdx.x;
    int tid = threadIdx.x;  // 128
    __shared__ int   s_idx[CAP];
    __shared__ float s_w[CAP];
    __shared__ float red[128];
    __shared__ float s_stat;
    __shared__ float part[8][16];
    int cnt = g_cnt[row];
    bool sparse = (cnt > 0 && cnt <= CAP);
    float s_i = g_s2[row];

    if (sparse) {
        for (int k = tid; k < cnt; k += 128) s_idx[k] = g_nbr[(size_t)row * CAP + k];
        __syncthreads();
        float m = -INFINITY;
        for (int k = tid; k < cnt; k += 128) {
            float lv = lrelu(s_i + __ldg(&g_t2[s_idx[k]]));
            s_w[k] = lv;
            m = fmaxf(m, lv);
        }
        red[tid] = m; __syncthreads();
        if (tid < 64) red[tid] = fmaxf(red[tid], red[tid + 64]);
        __syncthreads();
        if (tid < 32) {
            float mm = fmaxf(red[tid], red[tid + 32]);
#pragma unroll
            for (int o = 16; o > 0; o >>= 1) mm = fmaxf(mm, __shfl_xor_sync(0xffffffffu, mm, o));
            if (tid == 0) s_stat = mm;
        }
        __syncthreads();
        float mx = s_stat;
        float sum = 0.f;
        for (int k = tid; k < cnt; k += 128) {
            float e = expf(s_w[k] - mx);
            s_w[k] = e;
            sum += e;
        }
        __syncthreads();
        red[tid] = sum; __syncthreads();
        if (tid < 64) red[tid] += red[tid + 64];
        __syncthreads();
        if (tid < 32) {
            float ss = red[tid] + red[tid + 32];
#pragma unroll
            for (int o = 16; o > 0; o >>= 1) ss += __shfl_xor_sync(0xffffffffu, ss, o);
            if (tid == 0) s_stat = ss;
        }
        __syncthreads();
        float S = s_stat;
        // weighted sum: 8 neighbor phases x 16 cols
        int q = tid >> 4, c = tid & 15;
        float acc = 0.f;
        for (int k = q; k < cnt; k += 8)
            acc += s_w[k] * __ldg(&g_H2[(size_t)s_idx[k] * 16 + c]);
        part[q][c] = acc;
        __syncthreads();
        if (tid < 16) {
            float a = 0.f;
#pragma unroll
            for (int w = 0; w < 8; w++) a += part[w][tid];
            float v = eluf(a / S);
            float m16 = v;
#pragma unroll
            for (int o = 8; o > 0; o >>= 1) m16 = fmaxf(m16, __shfl_xor_sync(0xffffu, m16, o, 16));
            float e = expf(v - m16);
            float se = e;
#pragma unroll
            for (int o = 8; o > 0; o >>= 1) se += __shfl_xor_sync(0xffffu, se, o, 16);
            out[(size_t)row * 16 + tid] = e / se;
        }
    } else {
        const float* arow = adj + (size_t)row * NV;
        float m = -INFINITY;
        for (int j = tid; j < NV; j += 128) {
            float lv = lrelu(s_i + g_t2[j]);
            if (arow[j] == 0.f) lv += NEGV;
            m = fmaxf(m, lv);
        }
        red[tid] = m; __syncthreads();
        if (tid < 64) red[tid] = fmaxf(red[tid], red[tid + 64]);
        __syncthreads();
        if (tid < 32) {
            float mm = fmaxf(red[tid], red[tid + 32]);
#pragma unroll
            for (int o = 16; o > 0; o >>= 1) mm = fmaxf(mm, __shfl_xor_sync(0xffffffffu, mm, o));
            if (tid == 0) s_stat = mm;
        }
        __syncthreads();
        float mx = s_stat;
        float sum = 0.f;
        for (int j = tid; j < NV; j += 128) {
            float lv = lrelu(s_i + g_t2[j]);
            if (arow[j] == 0.f) lv += NEGV;
            sum += expf(lv - mx);
        }
        __syncthreads();
        red[tid] = sum; __syncthreads();
        if (tid < 64) red[tid] += red[tid + 64];
        __syncthreads();
        if (tid < 32) {
            float ss = red[tid] + red[tid + 32];
#pragma unroll
            for (int o = 16; o > 0; o >>= 1) ss += __shfl_xor_sync(0xffffffffu, ss, o);
            if (tid == 0) s_stat = ss;
        }
        __syncthreads();
        float S = s_stat;
        if (tid < 16) {
            float acc = 0.f;
            for (int j = 0; j < NV; j++) {
                float lv = lrelu(s_i + g_t2[j]);
                if (arow[j] == 0.f) lv += NEGV;
                acc += expf(lv - mx) * g_H2[(size_t)j * 16 + tid];
            }
            float v = eluf(acc / S);
            float m16 = v;
#pragma unroll
            for (int o = 8; o > 0; o >>= 1) m16 = fmaxf(m16, __shfl_xor_sync(0xffffu, m16, o, 16));
            float e = expf(v - m16);
            float se = e;
#pragma unroll
            for (int o = 8; o > 0; o >>= 1) se += __shfl_xor_sync(0xffffu, se, o, 16);
            out[(size_t)row * 16 + tid] = e / se;
        }
    }
}

// ---------------- launch ----------------
extern "C" void kernel_launch(void* const* d_in, const int* in_sizes, int n_in,
                              void* d_out, int out_size) {
    const float* adj  = (const float*)d_in[0];
    const float* feat = (const float*)d_in[1];
    const float* W0   = (const float*)d_in[2];
    const float* a1_0 = (const float*)d_in[3];
    const float* a2_0 = (const float*)d_in[4];
    const float* Wout = (const float*)d_in[5];
    const float* a1o  = (const float*)d_in[6];
    const float* a2o  = (const float*)d_in[7];
    float* out = (float*)d_out;

    k_weff<<<(NFEAT * NHEAD * NHID + 255) / 256, 256>>>(W0);
    k_main<<<GEMM_BLOCKS + NV, 256>>>(adj, feat, a1_0, a2_0);   // GEMM + adj scan overlapped
    k_attn_hidden<<<NV, 256>>>(adj);
    k_out_proj<<<NV / 16, 256>>>(Wout, a1o, a2o);
    k_attn_out<<<NV, 128>>>(adj, out);
}

// round 5
// speedup vs baseline: 1.4530x; 1.0432x over previous
#include <cuda_runtime.h>
#include <math.h>
#include <stdint.h>

#define NV      6144
#define NFEAT   128
#define NHID    64
#define NHEAD   4
#define NCLASS  16
#define CAP     256
#define ALPHA   0.2f
#define NEGV    (-1e10f)
#define AS_STRIDE 68
#define GEMM_BLOCKS 384   // (6144/64) row-tiles * 4 heads

// ---------------- device scratch ----------------
__device__ float g_Weff[NFEAT * NHEAD * NHID];
__device__ float g_Hh[(size_t)NV * NHEAD * NHID];
__device__ float g_s[NHEAD * NV];
__device__ float g_t[NHEAD * NV];
__device__ int   g_nbr[(size_t)NV * CAP];
__device__ int   g_cnt[NV];
__device__ float g_X2[(size_t)NV * NHEAD * NHID];
__device__ float g_H2[(size_t)NV * NCLASS];
__device__ float g_s2[NV];
__device__ float g_t2[NV];

__device__ __forceinline__ float lrelu(float x) { return x > 0.f ? x : ALPHA * x; }
__device__ __forceinline__ float eluf(float x)  { return x > 0.f ? x : (expf(x) - 1.f); }

// ---------------- K1: Weff ----------------
__global__ void k_weff(const float* __restrict__ W0) {
    int tid = blockIdx.x * blockDim.x + threadIdx.x;
    if (tid >= NFEAT * NHEAD * NHID) return;
    int k = tid >> 8, C = tid & 255;
    int h = C >> 6, c = C & 63;
    const float* base = W0 + (size_t)h * 512 * 64;
    float v = 0.f;
#pragma unroll
    for (int t = 0; t < 4; t++) v += base[(t * 128 + k) * 64 + c];
    g_Weff[k * 256 + C] = v;
}

// ---------------- K2 fat kernel: GEMM blocks + nbr-compaction blocks ----------------
__global__ void __launch_bounds__(256) k_main(const float* __restrict__ adj,
                                              const float* __restrict__ feat,
                                              const float* __restrict__ a1g,
                                              const float* __restrict__ a2g) {
    __shared__ float As[64 * AS_STRIDE];
    __shared__ float Bs[64 * 64];
    __shared__ int wsum[8];
    int tid = threadIdx.x;

    if (blockIdx.x < GEMM_BLOCKS) {
        int head = blockIdx.x & 3;
        int row0 = (blockIdx.x >> 2) * 64;
        int tr = tid >> 4, tc = tid & 15;
        float acc[4][4] = {};
        const float4* feat4 = reinterpret_cast<const float4*>(feat);
        const float4* weff4 = reinterpret_cast<const float4*>(g_Weff);
        for (int kc = 0; kc < 2; kc++) {
#pragma unroll
            for (int it = 0; it < 4; it++) {
                int idx = it * 256 + tid;
                int r = idx >> 4, c4 = idx & 15;
                float4 v = feat4[(size_t)(row0 + r) * 32 + kc * 16 + c4];
                *reinterpret_cast<float4*>(&As[r * AS_STRIDE + c4 * 4]) = v;
            }
#pragma unroll
            for (int it = 0; it < 4; it++) {
                int idx = it * 256 + tid;
                int k = idx >> 4, c4 = idx & 15;
                float4 v = weff4[(size_t)(kc * 64 + k) * 64 + head * 16 + c4];
                *reinterpret_cast<float4*>(&Bs[k * 64 + c4 * 4]) = v;
            }
            __syncthreads();
#pragma unroll 4
            for (int k = 0; k < 64; k++) {
                float4 bv = *reinterpret_cast<const float4*>(&Bs[k * 64 + tc * 4]);
                float a0 = As[(tr * 4 + 0) * AS_STRIDE + k];
                float a1 = As[(tr * 4 + 1) * AS_STRIDE + k];
                float a2 = As[(tr * 4 + 2) * AS_STRIDE + k];
                float a3 = As[(tr * 4 + 3) * AS_STRIDE + k];
                acc[0][0] += a0 * bv.x; acc[0][1] += a0 * bv.y; acc[0][2] += a0 * bv.z; acc[0][3] += a0 * bv.w;
                acc[1][0] += a1 * bv.x; acc[1][1] += a1 * bv.y; acc[1][2] += a1 * bv.z; acc[1][3] += a1 * bv.w;
                acc[2][0] += a2 * bv.x; acc[2][1] += a2 * bv.y; acc[2][2] += a2 * bv.z; acc[2][3] += a2 * bv.w;
                acc[3][0] += a3 * bv.x; acc[3][1] += a3 * bv.y; acc[3][2] += a3 * bv.z; acc[3][3] += a3 * bv.w;
            }
            __syncthreads();
        }
        float a1r[4], a2r[4];
#pragma unroll
        for (int n = 0; n < 4; n++) {
            a1r[n] = __ldg(&a1g[head * 64 + tc * 4 + n]);
            a2r[n] = __ldg(&a2g[head * 64 + tc * 4 + n]);
        }
        float sp[4], tp[4];
#pragma unroll
        for (int m = 0; m < 4; m++) {
            float4 o;
            o.x = acc[m][0]; o.y = acc[m][1]; o.z = acc[m][2]; o.w = acc[m][3];
            *reinterpret_cast<float4*>(&g_Hh[(size_t)(row0 + tr * 4 + m) * 256 + head * 64 + tc * 4]) = o;
            sp[m] = acc[m][0] * a1r[0] + acc[m][1] * a1r[1] + acc[m][2] * a1r[2] + acc[m][3] * a1r[3];
            tp[m] = acc[m][0] * a2r[0] + acc[m][1] * a2r[1] + acc[m][2] * a2r[2] + acc[m][3] * a2r[3];
        }
#pragma unroll
        for (int o = 8; o > 0; o >>= 1) {
#pragma unroll
            for (int m = 0; m < 4; m++) {
                sp[m] += __shfl_down_sync(0xffffffffu, sp[m], o, 16);
                tp[m] += __shfl_down_sync(0xffffffffu, tp[m], o, 16);
            }
        }
        if (tc == 0) {
#pragma unroll
            for (int m = 0; m < 4; m++) {
                g_s[head * NV + row0 + tr * 4 + m] = sp[m];
                g_t[head * NV + row0 + tr * 4 + m] = tp[m];
            }
        }
    } else {
        int row = blockIdx.x - GEMM_BLOCKS;
        int lane = tid & 31, wid = tid >> 5;
        const uint4* a4 = reinterpret_cast<const uint4*>(adj) + (size_t)row * (NV / 4);
        uint4 v[6];
#pragma unroll
        for (int it = 0; it < 6; it++) v[it] = __ldg(&a4[it * 256 + tid]);
        unsigned mask = 0;
#pragma unroll
        for (int it = 0; it < 6; it++) {
            if (v[it].x) mask |= 1u << (it * 4 + 0);
            if (v[it].y) mask |= 1u << (it * 4 + 1);
            if (v[it].z) mask |= 1u << (it * 4 + 2);
            if (v[it].w) mask |= 1u << (it * 4 + 3);
        }
        int cnt = __popc(mask);
        int incl = cnt;
#pragma unroll
        for (int o = 1; o < 32; o <<= 1) {
            int n = __shfl_up_sync(0xffffffffu, incl, o);
            if (lane >= o) incl += n;
        }
        if (lane == 31) wsum[wid] = incl;
        __syncthreads();
        int base = 0;
#pragma unroll
        for (int w = 0; w < 8; w++) if (w < wid) base += wsum[w];
        int pos = base + incl - cnt;
        int* out = g_nbr + (size_t)row * CAP;
        while (mask) {
            int b = __ffs(mask) - 1;
            mask &= mask - 1;
            if (pos < CAP) out[pos] = (b >> 2) * 1024 + tid * 4 + (b & 3);
            pos++;
        }
        if (tid == 255) g_cnt[row] = base + incl;
    }
}

// ---------------- K3: hidden sparse attention + elu -> g_X2 (neighbor-parallel) ----------------
__global__ void __launch_bounds__(256) k_attn_hidden(const float* __restrict__ adj) {
    int row = blockIdx.x;
    int tid = threadIdx.x;
    int g = tid >> 6, l = tid & 63;
    __shared__ int    s_idx[CAP];
    __shared__ float  s_w[NHEAD][CAP];
    __shared__ float  red[256];
    __shared__ float  s_stat[NHEAD];
    __shared__ float4 part[4][64];
    int cnt = g_cnt[row];
    bool sparse = (cnt > 0 && cnt <= CAP);
    if (sparse)
        for (int k = tid; k < cnt; k += 256) s_idx[k] = g_nbr[(size_t)row * CAP + k];
    __syncthreads();
    float s_i = g_s[g * NV + row];
    const float* tvec = g_t + g * NV;

    if (sparse) {
        float mx = -INFINITY;
        for (int k = l; k < cnt; k += 64) {
            float lv = lrelu(s_i + __ldg(&tvec[s_idx[k]]));
            s_w[g][k] = lv;
            mx = fmaxf(mx, lv);
        }
        red[tid] = mx; __syncthreads();
        if (l < 32) {
            float m = fmaxf(red[tid], red[tid + 32]);
#pragma unroll
            for (int o = 16; o > 0; o >>= 1) m = fmaxf(m, __shfl_xor_sync(0xffffffffu, m, o));
            if (l == 0) s_stat[g] = m;
        }
        __syncthreads();
        mx = s_stat[g];
        float sum = 0.f;
        for (int k = l; k < cnt; k += 64) {
            float e = expf(s_w[g][k] - mx);
            s_w[g][k] = e;
            sum += e;
        }
        __syncthreads();
        red[tid] = sum; __syncthreads();
        if (l < 32) {
            float s = red[tid] + red[tid + 32];
#pragma unroll
            for (int o = 16; o > 0; o >>= 1) s += __shfl_xor_sync(0xffffffffu, s, o);
            if (l == 0) s_stat[g] = s;
        }
        __syncthreads();
        int q = g;
        int c4 = l;
        int hh = c4 >> 4;
        float4 acc = make_float4(0.f, 0.f, 0.f, 0.f);
        const float4* hh4 = reinterpret_cast<const float4*>(g_Hh);
        for (int k = q; k < cnt; k += 4) {
            float w = s_w[hh][k];
            float4 v = __ldg(&hh4[(size_t)s_idx[k] * 64 + c4]);
            acc.x += w * v.x; acc.y += w * v.y; acc.z += w * v.z; acc.w += w * v.w;
        }
        part[q][c4] = acc;
        __syncthreads();
        if (q == 0) {
            float4 p0 = part[0][c4], p1 = part[1][c4], p2 = part[2][c4], p3 = part[3][c4];
            float S = s_stat[hh];
            float4 o;
            o.x = eluf((p0.x + p1.x + p2.x + p3.x) / S);
            o.y = eluf((p0.y + p1.y + p2.y + p3.y) / S);
            o.z = eluf((p0.z + p1.z + p2.z + p3.z) / S);
            o.w = eluf((p0.w + p1.w + p2.w + p3.w) / S);
            *reinterpret_cast<float4*>(&g_X2[(size_t)row * 256 + c4 * 4]) = o;
        }
    } else {
        const float* arow = adj + (size_t)row * NV;
        float mx = -INFINITY;
        for (int j = l; j < NV; j += 64) {
            float lv = lrelu(s_i + tvec[j]);
            if (arow[j] == 0.f) lv += NEGV;
            mx = fmaxf(mx, lv);
        }
        red[tid] = mx; __syncthreads();
        if (l < 32) {
            float m = fmaxf(red[tid], red[tid + 32]);
#pragma unroll
            for (int o = 16; o > 0; o >>= 1) m = fmaxf(m, __shfl_xor_sync(0xffffffffu, m, o));
            if (l == 0) s_stat[g] = m;
        }
        __syncthreads();
        mx = s_stat[g];
        float sum = 0.f;
        for (int j = l; j < NV; j += 64) {
            float lv = lrelu(s_i + tvec[j]);
            if (arow[j] == 0.f) lv += NEGV;
            sum += expf(lv - mx);
        }
        __syncthreads();
        red[tid] = sum; __syncthreads();
        if (l < 32) {
            float s = red[tid] + red[tid + 32];
#pragma unroll
            for (int o = 16; o > 0; o >>= 1) s += __shfl_xor_sync(0xffffffffu, s, o);
            if (l == 0) s_stat[g] = s;
        }
        __syncthreads();
        float S = s_stat[g];
        float acc = 0.f;
        const float* hb = g_Hh + g * 64 + l;
        for (int j = 0; j < NV; j++) {
            float lv = lrelu(s_i + tvec[j]);
            if (arow[j] == 0.f) lv += NEGV;
            acc += expf(lv - mx) * hb[(size_t)j * 256];
        }
        g_X2[(size_t)row * 256 + g * 64 + l] = eluf(acc / S);
    }
}

// ---------------- K4: g_H2 = g_X2 @ Wout; s2/t2  (warp per row, conflict-free) ----------------
#define WS_STRIDE 17
__global__ void __launch_bounds__(256) k_out_proj(const float* __restrict__ Wout,
                                                  const float* __restrict__ a1o,
                                                  const float* __restrict__ a2o) {
    __shared__ float Ws[256 * WS_STRIDE];   // padded: addr = k*17 + c, lane delta 17 -> 32 banks
    __shared__ float a1s[16], a2s[16];
    int tid = threadIdx.x;
    for (int i = tid; i < 256 * 16; i += 256) {
        int k = i >> 4, c = i & 15;
        Ws[k * WS_STRIDE + c] = Wout[i];
    }
    if (tid < 16) { a1s[tid] = a1o[tid]; a2s[tid] = a2o[tid]; }
    __syncthreads();
    int warp = tid >> 5, lane = tid & 31;
    int row = blockIdx.x * 8 + warp;
    const float* x = g_X2 + (size_t)row * 256;
    // lane owns k = lane + 32m, m=0..7  (coalesced LDG, MLP=8)
    float xv[8];
#pragma unroll
    for (int m = 0; m < 8; m++) xv[m] = __ldg(&x[lane + 32 * m]);
    float acc[16];
#pragma unroll
    for (int c = 0; c < 16; c++) acc[c] = 0.f;
#pragma unroll
    for (int m = 0; m < 8; m++) {
        const float* wrow = &Ws[(lane + 32 * m) * WS_STRIDE];
#pragma unroll
        for (int c = 0; c < 16; c++) acc[c] += xv[m] * wrow[c];
    }
#pragma unroll
    for (int o = 16; o > 0; o >>= 1) {
#pragma unroll
        for (int c = 0; c < 16; c++) acc[c] += __shfl_xor_sync(0xffffffffu, acc[c], o);
    }
    // all lanes now hold the full 16 sums
    if (lane < 16) {
        float h = acc[lane];
        g_H2[(size_t)row * 16 + lane] = h;
        float sa = h * a1s[lane], sb = h * a2s[lane];
#pragma unroll
        for (int o = 8; o > 0; o >>= 1) {
            sa += __shfl_xor_sync(0xffffu, sa, o, 16);
            sb += __shfl_xor_sync(0xffffu, sb, o, 16);
        }
        if (lane == 0) { g_s2[row] = sa; g_t2[row] = sb; }
    }
}

// ---------------- K5: output sparse attention + elu + class softmax ----------------
__global__ void __launch_bounds__(128) k_attn_out(const float* __restrict__ adj, float* __restrict__ out) {
    int row = blockIdx.x;
    int tid = threadIdx.x;  // 128
    __shared__ int   s_idx[CAP];
    __shared__ float s_w[CAP];
    __shared__ float red[128];
    __shared__ float s_stat;
    __shared__ float part[8][16];
    int cnt = g_cnt[row];
    bool sparse = (cnt > 0 && cnt <= CAP);
    float s_i = g_s2[row];

    if (sparse) {
        for (int k = tid; k < cnt; k += 128) s_idx[k] = g_nbr[(size_t)row * CAP + k];
        __syncthreads();
        float m = -INFINITY;
        for (int k = tid; k < cnt; k += 128) {
            float lv = lrelu(s_i + __ldg(&g_t2[s_idx[k]]));
            s_w[k] = lv;
            m = fmaxf(m, lv);
        }
        red[tid] = m; __syncthreads();
        if (tid < 64) red[tid] = fmaxf(red[tid], red[tid + 64]);
        __syncthreads();
        if (tid < 32) {
            float mm = fmaxf(red[tid], red[tid + 32]);
#pragma unroll
            for (int o = 16; o > 0; o >>= 1) mm = fmaxf(mm, __shfl_xor_sync(0xffffffffu, mm, o));
            if (tid == 0) s_stat = mm;
        }
        __syncthreads();
        float mx = s_stat;
        float sum = 0.f;
        for (int k = tid; k < cnt; k += 128) {
            float e = expf(s_w[k] - mx);
            s_w[k] = e;
            sum += e;
        }
        __syncthreads();
        red[tid] = sum; __syncthreads();
        if (tid < 64) red[tid] += red[tid + 64];
        __syncthreads();
        if (tid < 32) {
            float ss = red[tid] + red[tid + 32];
#pragma unroll
            for (int o = 16; o > 0; o >>= 1) ss += __shfl_xor_sync(0xffffffffu, ss, o);
            if (tid == 0) s_stat = ss;
        }
        __syncthreads();
        float S = s_stat;
        int q = tid >> 4, c = tid & 15;
        float acc = 0.f;
        for (int k = q; k < cnt; k += 8)
            acc += s_w[k] * __ldg(&g_H2[(size_t)s_idx[k] * 16 + c]);
        part[q][c] = acc;
        __syncthreads();
        if (tid < 16) {
            float a = 0.f;
#pragma unroll
            for (int w = 0; w < 8; w++) a += part[w][tid];
            float v = eluf(a / S);
            float m16 = v;
#pragma unroll
            for (int o = 8; o > 0; o >>= 1) m16 = fmaxf(m16, __shfl_xor_sync(0xffffu, m16, o, 16));
            float e = expf(v - m16);
            float se = e;
#pragma unroll
            for (int o = 8; o > 0; o >>= 1) se += __shfl_xor_sync(0xffffu, se, o, 16);
            out[(size_t)row * 16 + tid] = e / se;
        }
    } else {
        const float* arow = adj + (size_t)row * NV;
        float m = -INFINITY;
        for (int j = tid; j < NV; j += 128) {
            float lv = lrelu(s_i + g_t2[j]);
            if (arow[j] == 0.f) lv += NEGV;
            m = fmaxf(m, lv);
        }
        red[tid] = m; __syncthreads();
        if (tid < 64) red[tid] = fmaxf(red[tid], red[tid + 64]);
        __syncthreads();
        if (tid < 32) {
            float mm = fmaxf(red[tid], red[tid + 32]);
#pragma unroll
            for (int o = 16; o > 0; o >>= 1) mm = fmaxf(mm, __shfl_xor_sync(0xffffffffu, mm, o));
            if (tid == 0) s_stat = mm;
        }
        __syncthreads();
        float mx = s_stat;
        float sum = 0.f;
        for (int j = tid; j < NV; j += 128) {
            float lv = lrelu(s_i + g_t2[j]);
            if (arow[j] == 0.f) lv += NEGV;
            sum += expf(lv - mx);
        }
        __syncthreads();
        red[tid] = sum; __syncthreads();
        if (tid < 64) red[tid] += red[tid + 64];
        __syncthreads();
        if (tid < 32) {
            float ss = red[tid] + red[tid + 32];
#pragma unroll
            for (int o = 16; o > 0; o >>= 1) ss += __shfl_xor_sync(0xffffffffu, ss, o);
            if (tid == 0) s_stat = ss;
        }
        __syncthreads();
        float S = s_stat;
        if (tid < 16) {
            float acc = 0.f;
            for (int j = 0; j < NV; j++) {
                float lv = lrelu(s_i + g_t2[j]);
                if (arow[j] == 0.f) lv += NEGV;
                acc += expf(lv - mx) * g_H2[(size_t)j * 16 + tid];
            }
            float v = eluf(acc / S);
            float m16 = v;
#pragma unroll
            for (int o = 8; o > 0; o >>= 1) m16 = fmaxf(m16, __shfl_xor_sync(0xffffu, m16, o, 16));
            float e = expf(v - m16);
            float se = e;
#pragma unroll
            for (int o = 8; o > 0; o >>= 1) se += __shfl_xor_sync(0xffffu, se, o, 16);
            out[(size_t)row * 16 + tid] = e / se;
        }
    }
}

// ---------------- launch ----------------
extern "C" void kernel_launch(void* const* d_in, const int* in_sizes, int n_in,
                              void* d_out, int out_size) {
    const float* adj  = (const float*)d_in[0];
    const float* feat = (const float*)d_in[1];
    const float* W0   = (const float*)d_in[2];
    const float* a1_0 = (const float*)d_in[3];
    const float* a2_0 = (const float*)d_in[4];
    const float* Wout = (const float*)d_in[5];
    const float* a1o  = (const float*)d_in[6];
    const float* a2o  = (const float*)d_in[7];
    float* out = (float*)d_out;

    k_weff<<<(NFEAT * NHEAD * NHID + 255) / 256, 256>>>(W0);
    k_main<<<GEMM_BLOCKS + NV, 256>>>(adj, feat, a1_0, a2_0);
    k_attn_hidden<<<NV, 256>>>(adj);
    k_out_proj<<<NV / 8, 256>>>(Wout, a1o, a2o);
    k_attn_out<<<NV, 128>>>(adj, out);
}